// round 1
// baseline (speedup 1.0000x reference)
#include <cuda_runtime.h>
#include <math.h>

#define BB 16
#define NN 2000
#define CC 81
#define NPAD 2048
#define MAXC 64
#define MAXI 100            // MAX_INST
#define MIN_CONF 0.7f
#define NMS_TH 0.3f

// Scratch (static device globals — no allocation at runtime)
__device__ float4        g_ref[BB * NPAD];      // refined clipped boxes, unsorted
__device__ float         g_nscore[BB * NPAD];   // nms score (-1 if invalid)
__device__ int           g_cls[BB * NPAD];
__device__ float4        g_sref[BB * NPAD];     // sorted by score desc
__device__ float         g_sscore[BB * NPAD];
__device__ int           g_scls[BB * NPAD];
__device__ unsigned char g_keep[BB * NPAD];

// ---------------------------------------------------------------------------
// K1: one warp per ROI. Coalesced argmax over 81 probs (first-max tiebreak),
// gather class-specific delta, apply/clip box, validity.
// ---------------------------------------------------------------------------
__global__ void k_classify(const float* __restrict__ rois,
                           const float* __restrict__ probs,
                           const float* __restrict__ deltas) {
    int gw   = (blockIdx.x * blockDim.x + threadIdx.x) >> 5;   // global warp = (b*NN+n)
    int lane = threadIdx.x & 31;
    if (gw >= BB * NN) return;
    int b = gw / NN;
    int n = gw - b * NN;

    const float* p = probs + (size_t)gw * CC;
    float bv = -1.0f;
    int   bi = 0;
#pragma unroll
    for (int k = 0; k < 3; k++) {
        int c = lane + k * 32;
        if (c < CC) {
            float v = __ldg(p + c);
            if (v > bv) { bv = v; bi = c; }      // strict > keeps lowest index per lane
        }
    }
    // reduce: max value, lowest index on tie (matches jnp.argmax)
    for (int off = 16; off; off >>= 1) {
        float ov = __shfl_down_sync(0xffffffffu, bv, off);
        int   oi = __shfl_down_sync(0xffffffffu, bi, off);
        if (ov > bv || (ov == bv && oi < bi)) { bv = ov; bi = oi; }
    }

    if (lane == 0) {
        float4 r = __ldg((const float4*)rois + gw);
        float4 d = __ldg((const float4*)deltas + ((size_t)gw * CC + bi));
        float h  = r.z - r.x;
        float w  = r.w - r.y;
        float cy = r.x + 0.5f * h;
        float cx = r.y + 0.5f * w;
        cy += d.x * 0.1f * h;           // BBOX_STD = (0.1, 0.1, 0.2, 0.2)
        cx += d.y * 0.1f * w;
        h  *= expf(d.z * 0.2f);
        w  *= expf(d.w * 0.2f);
        float y1 = fminf(fmaxf(cy - 0.5f * h, 0.f), 1.f);
        float x1 = fminf(fmaxf(cx - 0.5f * w, 0.f), 1.f);
        float y2 = fminf(fmaxf(cy + 0.5f * h, 0.f), 1.f);
        float x2 = fminf(fmaxf(cx + 0.5f * w, 0.f), 1.f);

        bool valid = (bi > 0) && (bv >= MIN_CONF);
        int  o = b * NPAD + n;
        g_ref[o]    = make_float4(y1, x1, y2, x2);
        g_cls[o]    = bi;
        g_nscore[o] = valid ? bv : -1.0f;
    }
}

// ---------------------------------------------------------------------------
// K2: per-batch bitonic sort of 2048 (score, idx) pairs in shared memory.
// Comparator (score desc, idx asc) == stable jnp.argsort(-scores).
// Then scatter-gather sorted payload arrays.
// ---------------------------------------------------------------------------
__global__ void k_sort() {
    __shared__ float key[NPAD];
    __shared__ int   idx[NPAD];
    int b = blockIdx.x;
    int t = threadIdx.x;   // 1024 threads

    for (int s = t; s < NPAD; s += 1024) {
        key[s] = (s < NN) ? g_nscore[b * NPAD + s] : -3.0f;   // pad sinks below -1
        idx[s] = s;
    }
    __syncthreads();

    for (int k = 2; k <= NPAD; k <<= 1) {
        for (int j = k >> 1; j > 0; j >>= 1) {
            int  i    = ((t & ~(j - 1)) << 1) | (t & (j - 1));
            int  pp   = i | j;
            bool desc = ((i & k) == 0);
            float ki = key[i], kp = key[pp];
            int   ii = idx[i], ip = idx[pp];
            bool igtp = (ki > kp) || (ki == kp && ii < ip);
            if (desc ? !igtp : igtp) {
                key[i] = kp; key[pp] = ki;
                idx[i] = ip; idx[pp] = ii;
            }
            __syncthreads();
        }
    }

    for (int s = t; s < NPAD; s += 1024) {
        int   j  = idx[s];
        float sc = key[s];
        int   o  = b * NPAD + s;
        g_sscore[o] = sc;
        if (j < NN) {
            g_sref[o] = g_ref[b * NPAD + j];
            g_scls[o] = g_cls[b * NPAD + j];
        } else {
            g_sref[o] = make_float4(0.f, 0.f, 0.f, 0.f);
            g_scls[o] = 0;
        }
    }
}

// ---------------------------------------------------------------------------
// K3: one warp per (batch, class). Cross-class IoU is exactly 0 (class offset
// 2.0 on clipped [0,1] boxes), so greedy NMS decomposes per class. Collect the
// (score>0, cls==c) candidates in sorted order via ballot compaction, then a
// tiny serial greedy over <=64 boxes held in shared memory.
// ---------------------------------------------------------------------------
__global__ void k_nms() {
    __shared__ float4        sbox [8][MAXC];
    __shared__ float         sarea[8][MAXC];
    __shared__ int           spos [8][MAXC];
    __shared__ unsigned char skeep[8][MAXC];

    int w    = threadIdx.x >> 5;
    int lane = threadIdx.x & 31;
    int gw   = blockIdx.x * 8 + w;
    if (gw >= BB * 80) return;
    int b = gw / 80;
    int c = (gw % 80) + 1;   // classes 1..80 (class 0 is never valid)

    int cnt = 0;
    for (int base = 0; base < NN && cnt < MAXC; base += 32) {
        int    s  = base + lane;
        bool   m  = false;
        float4 bx = make_float4(0.f, 0.f, 0.f, 0.f);
        if (s < NN) {
            int o = b * NPAD + s;
            if (g_sscore[o] > 0.0f && g_scls[o] == c) { m = true; bx = g_sref[o]; }
        }
        unsigned bal = __ballot_sync(0xffffffffu, m);
        int pos = cnt + __popc(bal & ((1u << lane) - 1u));
        if (m && pos < MAXC) { sbox[w][pos] = bx; spos[w][pos] = s; }
        cnt += __popc(bal);
    }
    if (cnt > MAXC) cnt = MAXC;
    __syncwarp();

    for (int e = lane; e < cnt; e += 32) {
        float4 a = sbox[w][e];
        sarea[w][e] = (a.z - a.x) * (a.w - a.y);
        skeep[w][e] = 1;
    }
    __syncwarp();

    for (int i = 1; i < cnt; i++) {
        float4 bi_ = sbox[w][i];
        float  ai  = sarea[w][i];
        bool   sup = false;
        for (int e = lane; e < i; e += 32) {
            if (skeep[w][e]) {
                float4 a  = sbox[w][e];
                float ih  = fmaxf(fminf(a.z, bi_.z) - fmaxf(a.x, bi_.x), 0.f);
                float iw  = fmaxf(fminf(a.w, bi_.w) - fmaxf(a.y, bi_.y), 0.f);
                float inter = ih * iw;
                float uni   = sarea[w][e] + ai - inter;
                if (inter > NMS_TH * fmaxf(uni, 1e-8f)) sup = true;
            }
        }
        unsigned anyb = __ballot_sync(0xffffffffu, sup);
        if (lane == 0) skeep[w][i] = (anyb == 0) ? 1 : 0;
        __syncwarp();
    }

    for (int e = lane; e < cnt; e += 32)
        g_keep[b * NPAD + spos[w][e]] = skeep[w][e];
}

// ---------------------------------------------------------------------------
// K4: per-batch compaction. keep flags (score>0 && kept) are already in
// descending-score order; prefix-sum via ballot/popcount, emit first 100 rows,
// zero-pad the rest (output poisoned to 0xAA by harness).
// ---------------------------------------------------------------------------
__global__ void k_output(float* __restrict__ out) {
    __shared__ int wcnt[32];
    __shared__ int woff[32];
    int b    = blockIdx.x;
    int t    = threadIdx.x;   // 1024
    int w    = t >> 5;
    int lane = t & 31;

    float* ob = out + b * (MAXI * 6);
    for (int e = t; e < MAXI * 6; e += 1024) ob[e] = 0.0f;

    int s0 = w * 64 + lane;
    int s1 = s0 + 32;
    int o0 = b * NPAD + s0;
    int o1 = b * NPAD + s1;
    bool f0 = (g_sscore[o0] > 0.0f) && g_keep[o0];
    bool f1 = (g_sscore[o1] > 0.0f) && g_keep[o1];
    unsigned b0 = __ballot_sync(0xffffffffu, f0);
    unsigned b1 = __ballot_sync(0xffffffffu, f1);
    if (lane == 0) wcnt[w] = __popc(b0) + __popc(b1);
    __syncthreads();

    if (w == 0) {
        int v = wcnt[lane], x = v;
        for (int d = 1; d < 32; d <<= 1) {
            int y = __shfl_up_sync(0xffffffffu, x, d);
            if (lane >= d) x += y;
        }
        woff[lane] = x - v;   // exclusive prefix
    }
    __syncthreads();

    int base = woff[w];
    int p0 = base + __popc(b0 & ((1u << lane) - 1u));
    int p1 = base + __popc(b0) + __popc(b1 & ((1u << lane) - 1u));

    if (f0 && p0 < MAXI) {
        float4 r = g_sref[o0];
        float* row = ob + p0 * 6;
        row[0] = r.x; row[1] = r.y; row[2] = r.z; row[3] = r.w;
        row[4] = (float)g_scls[o0]; row[5] = g_sscore[o0];
    }
    if (f1 && p1 < MAXI) {
        float4 r = g_sref[o1];
        float* row = ob + p1 * 6;
        row[0] = r.x; row[1] = r.y; row[2] = r.z; row[3] = r.w;
        row[4] = (float)g_scls[o1]; row[5] = g_sscore[o1];
    }
}

// ---------------------------------------------------------------------------
extern "C" void kernel_launch(void* const* d_in, const int* in_sizes, int n_in,
                              void* d_out, int out_size) {
    const float* rois   = nullptr;
    const float* probs  = nullptr;
    const float* deltas = nullptr;
    for (int i = 0; i < n_in; i++) {
        if      (in_sizes[i] == BB * NN * 4)      rois   = (const float*)d_in[i];
        else if (in_sizes[i] == BB * NN * CC)     probs  = (const float*)d_in[i];
        else if (in_sizes[i] == BB * NN * CC * 4) deltas = (const float*)d_in[i];
    }
    float* out = (float*)d_out;

    k_classify<<<(BB * NN + 7) / 8, 256>>>(rois, probs, deltas);  // 1 warp / ROI
    k_sort    <<<BB, 1024>>>();
    k_nms     <<<(BB * 80 + 7) / 8, 256>>>();                     // 1 warp / (b,class)
    k_output  <<<BB, 1024>>>(out);
}

// round 2
// speedup vs baseline: 1.7401x; 1.7401x over previous
#include <cuda_runtime.h>
#include <math.h>

#define BB 16
#define NN 2000
#define CC 81
#define NPAD 2048
#define MAXC 64
#define MAXI 100
#define MIN_CONF 0.7f
#define NMS_TH 0.3f
#define FULL 0xffffffffu

typedef unsigned long long ull;

// Scratch (static device globals — no runtime allocation)
__device__ float4 g_bx[BB * NPAD];   // refined clipped boxes
__device__ float  g_sc[BB * NPAD];   // score (-1 if invalid)
__device__ int    g_cl[BB * NPAD];   // argmax class id

// ---------------------------------------------------------------------------
// K1: one warp per ROI. Coalesced argmax over 81 probs (first-max tiebreak),
// gather class-specific delta, apply/clip box, validity. Full-chip grid.
// ---------------------------------------------------------------------------
__global__ void k_classify(const float* __restrict__ rois,
                           const float* __restrict__ probs,
                           const float* __restrict__ deltas) {
    int gw   = (blockIdx.x * blockDim.x + threadIdx.x) >> 5;
    int lane = threadIdx.x & 31;
    if (gw >= BB * NN) return;
    int b = gw / NN;
    int n = gw - b * NN;

    const float* p = probs + (size_t)gw * CC;
    float bv = -1.0f;
    int   bi = 0;
#pragma unroll
    for (int k = 0; k < 3; k++) {
        int c = lane + k * 32;
        if (c < CC) {
            float v = __ldg(p + c);
            if (v > bv) { bv = v; bi = c; }
        }
    }
    for (int off = 16; off; off >>= 1) {
        float ov = __shfl_down_sync(FULL, bv, off);
        int   oi = __shfl_down_sync(FULL, bi, off);
        if (ov > bv || (ov == bv && oi < bi)) { bv = ov; bi = oi; }
    }

    if (lane == 0) {
        float4 r = __ldg((const float4*)rois + gw);
        float4 d = __ldg((const float4*)deltas + ((size_t)gw * CC + bi));
        float h  = r.z - r.x;
        float w  = r.w - r.y;
        float cy = r.x + 0.5f * h;
        float cx = r.y + 0.5f * w;
        cy += d.x * 0.1f * h;
        cx += d.y * 0.1f * w;
        h  *= expf(d.z * 0.2f);
        w  *= expf(d.w * 0.2f);
        float y1 = fminf(fmaxf(cy - 0.5f * h, 0.f), 1.f);
        float x1 = fminf(fmaxf(cx - 0.5f * w, 0.f), 1.f);
        float y2 = fminf(fmaxf(cy + 0.5f * h, 0.f), 1.f);
        float x2 = fminf(fmaxf(cx + 0.5f * w, 0.f), 1.f);

        bool valid = (bi > 0) && (bv >= MIN_CONF);
        int  o = b * NPAD + n;
        g_bx[o] = make_float4(y1, x1, y2, x2);
        g_cl[o] = bi;
        g_sc[o] = valid ? bv : -1.0f;
    }
}

// ---------------------------------------------------------------------------
// Warp-register bitonic sort of 64 ull keys, descending. Element e0=lane,
// e1=lane+32. Pads (key 0) sink to the end.
// ---------------------------------------------------------------------------
__device__ __forceinline__ void bsort64(ull& k0, ull& k1, int lane) {
#pragma unroll
    for (int kk = 2; kk <= 64; kk <<= 1) {
#pragma unroll
        for (int d = kk >> 1; d > 0; d >>= 1) {
            if (d == 32) {
                // partner is the other register of the same lane; e0 lower, asc
                ull mx = k0 > k1 ? k0 : k1;
                ull mn = k0 > k1 ? k1 : k0;
                k0 = mx; k1 = mn;               // (e0&64)==0 -> asc -> lower keeps max
            } else {
                ull o0 = __shfl_xor_sync(FULL, k0, d);
                ull o1 = __shfl_xor_sync(FULL, k1, d);
                bool lower = ((lane & d) == 0);
                bool asc0  = ((lane & kk) == 0);
                bool asc1  = (((lane + 32) & kk) == 0);
                k0 = (asc0 == lower) ? (k0 > o0 ? k0 : o0) : (k0 > o0 ? o0 : k0);
                k1 = (asc1 == lower) ? (k1 > o1 ? k1 : o1) : (k1 > o1 ? o1 : k1);
            }
        }
    }
}

// ---------------------------------------------------------------------------
// K2: one block per batch (1024 thr). Bin by class (shared atomics), per-class
// warp NMS (register bitonic + greedy), histogram radix-select of top-100,
// small 256-sort, emit output. No global 2048-sort.
// ---------------------------------------------------------------------------
__global__ void __launch_bounds__(1024, 1) k_finish(float* __restrict__ out) {
    __shared__ float          ssc[NPAD];
    __shared__ int            scl[NPAD];
    __shared__ unsigned short slots[80 * MAXC];
    __shared__ int            scnt[80];
    __shared__ unsigned char  skp[NPAD];
    __shared__ int            hist[2048];
    __shared__ ull            cand[256];
    __shared__ int            wtot[32];
    __shared__ int            wexc[32];
    __shared__ int            s_ncand;
    __shared__ int            s_bstar;

    int b    = blockIdx.x;
    int t    = threadIdx.x;
    int w    = t >> 5;
    int lane = t & 31;
    int gb   = b * NPAD;

    float* ob = out + b * (MAXI * 6);

    // init
    for (int i = t; i < NPAD; i += 1024) {
        ssc[i]  = (i < NN) ? g_sc[gb + i] : -1.0f;
        scl[i]  = (i < NN) ? g_cl[gb + i] : 0;
        skp[i]  = 0;
        hist[i] = 0;
    }
    if (t < 80) scnt[t] = 0;
    if (t == 0) { s_ncand = 0; s_bstar = 0; }
    for (int i = t; i < MAXI * 6; i += 1024) ob[i] = 0.0f;
    __syncthreads();

    // bin candidates by class (order-agnostic; restored by per-class sort)
    for (int i = t; i < NN; i += 1024) {
        if (ssc[i] > 0.0f) {
            int c = scl[i] - 1;                     // 0..79
            int p = atomicAdd(&scnt[c], 1);
            if (p < MAXC) slots[c * MAXC + p] = (unsigned short)i;
        }
    }
    __syncthreads();

    // per-class NMS: warp w handles classes w, w+32, w+64
    for (int c = w; c < 80; c += 32) {
        int n_c = min(scnt[c], MAXC);
        ull k0 = 0, k1 = 0;
        if (lane < n_c) {
            int idx = slots[c * MAXC + lane];
            k0 = ((ull)__float_as_uint(ssc[idx]) << 32) | (ull)(0xFFFFFFFFu - (unsigned)idx);
        }
        if (lane + 32 < n_c) {
            int idx = slots[c * MAXC + lane + 32];
            k1 = ((ull)__float_as_uint(ssc[idx]) << 32) | (ull)(0xFFFFFFFFu - (unsigned)idx);
        }
        bsort64(k0, k1, lane);

        bool kp0 = (lane < n_c);
        bool kp1 = (lane + 32 < n_c);
        int  i0  = (int)(0xFFFFFFFFu - (unsigned)k0);
        int  i1  = (int)(0xFFFFFFFFu - (unsigned)k1);
        float4 B0 = kp0 ? g_bx[gb + i0] : make_float4(0.f, 0.f, 0.f, 0.f);
        float4 B1 = kp1 ? g_bx[gb + i1] : make_float4(0.f, 0.f, 0.f, 0.f);
        float a0 = (B0.z - B0.x) * (B0.w - B0.y);
        float a1 = (B1.z - B1.x) * (B1.w - B1.y);

        for (int i = 1; i < n_c; i++) {
            int  src = i & 31;
            bool hi  = (i >= 32);
            float by1 = __shfl_sync(FULL, hi ? B1.x : B0.x, src);
            float bx1 = __shfl_sync(FULL, hi ? B1.y : B0.y, src);
            float by2 = __shfl_sync(FULL, hi ? B1.z : B0.z, src);
            float bx2 = __shfl_sync(FULL, hi ? B1.w : B0.w, src);
            float bar = __shfl_sync(FULL, hi ? a1   : a0,   src);

            bool sup = false;
            if (kp0 && lane < i) {
                float ih = fmaxf(fminf(B0.z, by2) - fmaxf(B0.x, by1), 0.f);
                float iw = fmaxf(fminf(B0.w, bx2) - fmaxf(B0.y, bx1), 0.f);
                float inter = ih * iw;
                if (inter > NMS_TH * fmaxf(a0 + bar - inter, 1e-8f)) sup = true;
            }
            if (kp1 && lane + 32 < i) {
                float ih = fmaxf(fminf(B1.z, by2) - fmaxf(B1.x, by1), 0.f);
                float iw = fmaxf(fminf(B1.w, bx2) - fmaxf(B1.y, bx1), 0.f);
                float inter = ih * iw;
                if (inter > NMS_TH * fmaxf(a1 + bar - inter, 1e-8f)) sup = true;
            }
            bool any = (__ballot_sync(FULL, sup) != 0);
            if (lane == src) {
                if (hi) kp1 = kp1 && !any;
                else    kp0 = kp0 && !any;
            }
        }
        if (kp0) skp[i0] = 1;
        if (kp1) skp[i1] = 1;
    }
    __syncthreads();

    // histogram of kept scores on float bits (scores in (0.7,1) -> [0.5,1))
    for (int i = t; i < NN; i += 1024) {
        if (skp[i]) {
            unsigned bits = __float_as_uint(ssc[i]);
            int bk = (int)((bits - 0x3F000000u) >> 12);
            bk = min(2047, max(0, bk));
            atomicAdd(&hist[bk], 1);
        }
    }
    __syncthreads();

    // suffix sums: S[b] = sum_{b' >= b} hist[b']; find b* = max b with S[b] >= 100
    {
        int h0 = hist[w * 64 + lane];
        int h1 = hist[w * 64 + 32 + lane];
        int s1 = h1;
        for (int d = 1; d < 32; d <<= 1) {
            int v = __shfl_down_sync(FULL, s1, d);
            if (lane + d < 32) s1 += v;
        }
        int s0 = h0;
        for (int d = 1; d < 32; d <<= 1) {
            int v = __shfl_down_sync(FULL, s0, d);
            if (lane + d < 32) s0 += v;
        }
        s0 += __shfl_sync(FULL, s1, 0);   // add upper-half chunk total
        if (lane == 0) wtot[w] = s0;      // chunk total
        __syncthreads();
        if (w == 0) {
            int v = wtot[lane];
            int si = v;
            for (int d = 1; d < 32; d <<= 1) {
                int x = __shfl_down_sync(FULL, si, d);
                if (lane + d < 32) si += x;
            }
            wexc[lane] = si - v;          // exclusive suffix (chunks above w)
        }
        __syncthreads();
        int base = wexc[w];
        int S0 = s0 + base;
        int S1 = s1 + base;
        if (S0 >= MAXI && S0 - h0 < MAXI) s_bstar = w * 64 + lane;
        if (S1 >= MAXI && S1 - h1 < MAXI) s_bstar = w * 64 + 32 + lane;
    }
    __syncthreads();

    // collect survivors with bucket >= b*  (count in [100, 100+hist[b*]))
    unsigned tbits = 0x3F000000u + ((unsigned)s_bstar << 12);
    for (int i = t; i < NN; i += 1024) {
        if (skp[i] && __float_as_uint(ssc[i]) >= tbits) {
            int p = atomicAdd(&s_ncand, 1);
            if (p < 256)
                cand[p] = ((ull)__float_as_uint(ssc[i]) << 32) | (ull)(0xFFFFFFFFu - (unsigned)i);
        }
    }
    __syncthreads();
    int m = min(s_ncand, 256);
    for (int i = t; i < 256; i += 1024)
        if (i >= m) cand[i] = 0;
    __syncthreads();

    // bitonic sort 256 descending (128 comparator threads)
    for (int k = 2; k <= 256; k <<= 1) {
        for (int j = k >> 1; j > 0; j >>= 1) {
            if (t < 128) {
                int  i  = ((t & ~(j - 1)) << 1) | (t & (j - 1));
                int  p  = i | j;
                bool de = ((i & k) == 0);
                ull a = cand[i], c2 = cand[p];
                bool swp = de ? (a < c2) : (a > c2);
                if (swp) { cand[i] = c2; cand[p] = a; }
            }
            __syncthreads();
        }
    }

    // emit top-100 rows
    int R = min(MAXI, m);
    if (t < R) {
        ull key = cand[t];
        int idx = (int)(0xFFFFFFFFu - (unsigned)key);
        float sc = __uint_as_float((unsigned)(key >> 32));
        float4 bx = g_bx[gb + idx];
        float* row = ob + t * 6;
        row[0] = bx.x; row[1] = bx.y; row[2] = bx.z; row[3] = bx.w;
        row[4] = (float)scl[idx]; row[5] = sc;
    }
}

// ---------------------------------------------------------------------------
extern "C" void kernel_launch(void* const* d_in, const int* in_sizes, int n_in,
                              void* d_out, int out_size) {
    const float* rois   = nullptr;
    const float* probs  = nullptr;
    const float* deltas = nullptr;
    for (int i = 0; i < n_in; i++) {
        if      (in_sizes[i] == BB * NN * 4)      rois   = (const float*)d_in[i];
        else if (in_sizes[i] == BB * NN * CC)     probs  = (const float*)d_in[i];
        else if (in_sizes[i] == BB * NN * CC * 4) deltas = (const float*)d_in[i];
    }
    float* out = (float*)d_out;

    k_classify<<<(BB * NN + 7) / 8, 256>>>(rois, probs, deltas);
    k_finish  <<<BB, 1024>>>(out);
}

// round 3
// speedup vs baseline: 2.8364x; 1.6301x over previous
#include <cuda_runtime.h>
#include <math.h>

#define BB 16
#define NN 2000
#define CC 81
#define NPAD 2048
#define MAXC 64
#define MAXI 100
#define MIN_CONF 0.7f
#define NMS_TH 0.3f
#define FULL 0xffffffffu

typedef unsigned long long ull;

// Scratch (static device globals — no runtime allocation).
// g_cnt / g_keep rely on zero-init; k_nms restores g_cnt to 0 each run, and
// g_keep entries for candidates are rewritten every run (others stay 0).
__device__ float4         g_bx[BB * NPAD];
__device__ float          g_sc[BB * NPAD];
__device__ int            g_cl[BB * NPAD];
__device__ unsigned char  g_keep[BB * NPAD];
__device__ int            g_cnt[BB * 80];
__device__ unsigned short g_slot[BB * 80 * MAXC];

// ---------------------------------------------------------------------------
// K1: one warp per ROI. Argmax over 81 probs (first-max tiebreak), gather
// class delta, refine+clip, validity. Valid ROIs are binned into per-(b,class)
// slot lists via global atomics (order restored later by key sort).
// ---------------------------------------------------------------------------
__global__ void k_classify(const float* __restrict__ rois,
                           const float* __restrict__ probs,
                           const float* __restrict__ deltas) {
    int gw   = (blockIdx.x * blockDim.x + threadIdx.x) >> 5;
    int lane = threadIdx.x & 31;
    if (gw >= BB * NN) return;
    int b = gw / NN;
    int n = gw - b * NN;

    const float* p = probs + (size_t)gw * CC;
    float bv = -1.0f;
    int   bi = 0;
#pragma unroll
    for (int k = 0; k < 3; k++) {
        int c = lane + k * 32;
        if (c < CC) {
            float v = __ldg(p + c);
            if (v > bv) { bv = v; bi = c; }
        }
    }
    for (int off = 16; off; off >>= 1) {
        float ov = __shfl_down_sync(FULL, bv, off);
        int   oi = __shfl_down_sync(FULL, bi, off);
        if (ov > bv || (ov == bv && oi < bi)) { bv = ov; bi = oi; }
    }

    if (lane == 0) {
        float4 r = __ldg((const float4*)rois + gw);
        float4 d = __ldg((const float4*)deltas + ((size_t)gw * CC + bi));
        float h  = r.z - r.x;
        float w  = r.w - r.y;
        float cy = r.x + 0.5f * h;
        float cx = r.y + 0.5f * w;
        cy += d.x * 0.1f * h;
        cx += d.y * 0.1f * w;
        h  *= expf(d.z * 0.2f);
        w  *= expf(d.w * 0.2f);
        float y1 = fminf(fmaxf(cy - 0.5f * h, 0.f), 1.f);
        float x1 = fminf(fmaxf(cx - 0.5f * w, 0.f), 1.f);
        float y2 = fminf(fmaxf(cy + 0.5f * h, 0.f), 1.f);
        float x2 = fminf(fmaxf(cx + 0.5f * w, 0.f), 1.f);

        bool valid = (bi > 0) && (bv >= MIN_CONF);
        int  o = b * NPAD + n;
        g_bx[o] = make_float4(y1, x1, y2, x2);
        g_cl[o] = bi;
        g_sc[o] = valid ? bv : -1.0f;
        if (valid) {
            int cidx = b * 80 + (bi - 1);
            int pos  = atomicAdd(&g_cnt[cidx], 1);
            if (pos < MAXC) g_slot[cidx * MAXC + pos] = (unsigned short)n;
        }
    }
}

// ---------------------------------------------------------------------------
// Warp-register bitonic sort of 64 ull keys, descending (e0=lane, e1=lane+32).
// ---------------------------------------------------------------------------
__device__ __forceinline__ void bsort64(ull& k0, ull& k1, int lane) {
#pragma unroll
    for (int kk = 2; kk <= 64; kk <<= 1) {
#pragma unroll
        for (int d = kk >> 1; d > 0; d >>= 1) {
            if (d == 32) {
                ull mx = k0 > k1 ? k0 : k1;
                ull mn = k0 > k1 ? k1 : k0;
                k0 = mx; k1 = mn;
            } else {
                ull o0 = __shfl_xor_sync(FULL, k0, d);
                ull o1 = __shfl_xor_sync(FULL, k1, d);
                bool lower = ((lane & d) == 0);
                bool asc0  = ((lane & kk) == 0);
                bool asc1  = (((lane + 32) & kk) == 0);
                k0 = (asc0 == lower) ? (k0 > o0 ? k0 : o0) : (k0 > o0 ? o0 : k0);
                k1 = (asc1 == lower) ? (k1 > o1 ? k1 : o1) : (k1 > o1 ? o1 : k1);
            }
        }
    }
}

// ---------------------------------------------------------------------------
// K2: one warp per (batch,class). Read the <=64 pre-binned candidates, sort by
// (score desc, idx asc) in registers, compute per-element suppression bitmasks
// in one parallel pass, resolve greedy fixpoint serially on lane 0.
// Cross-class IoU is exactly 0 (class offset 2 on clipped [0,1] boxes), so
// this equals the reference's global greedy NMS.
// ---------------------------------------------------------------------------
__global__ void k_nms() {
    __shared__ float4 sbox[8][MAXC];
    __shared__ float  sar [8][MAXC];
    __shared__ ull    smsk[8][MAXC];

    int w    = threadIdx.x >> 5;
    int lane = threadIdx.x & 31;
    int gw   = blockIdx.x * 8 + w;
    if (gw >= BB * 80) return;
    int b  = gw / 80;
    int gb = b * NPAD;

    int cnt = min(g_cnt[gw], MAXC);

    ull k0 = 0, k1 = 0;
    if (lane < cnt) {
        int idx = g_slot[gw * MAXC + lane];
        k0 = ((ull)__float_as_uint(g_sc[gb + idx]) << 32) | (ull)(0xFFFFFFFFu - (unsigned)idx);
    }
    if (lane + 32 < cnt) {
        int idx = g_slot[gw * MAXC + lane + 32];
        k1 = ((ull)__float_as_uint(g_sc[gb + idx]) << 32) | (ull)(0xFFFFFFFFu - (unsigned)idx);
    }
    bsort64(k0, k1, lane);

    bool v0 = (lane < cnt);
    bool v1 = (lane + 32 < cnt);
    int  i0 = (int)(0xFFFFFFFFu - (unsigned)k0);
    int  i1 = (int)(0xFFFFFFFFu - (unsigned)k1);
    float4 B0 = v0 ? g_bx[gb + i0] : make_float4(0.f, 0.f, 0.f, 0.f);
    float4 B1 = v1 ? g_bx[gb + i1] : make_float4(0.f, 0.f, 0.f, 0.f);
    float a0 = (B0.z - B0.x) * (B0.w - B0.y);
    float a1 = (B1.z - B1.x) * (B1.w - B1.y);
    sbox[w][lane]      = B0;  sar[w][lane]      = a0;
    sbox[w][lane + 32] = B1;  sar[w][lane + 32] = a1;
    __syncwarp();

    // suppression masks: m[e] has bit j set iff j < e and IoU(e, j) > thresh
    ull m0 = 0, m1 = 0;
#pragma unroll 4
    for (int j = 0; j < cnt; j++) {
        float4 bj = sbox[w][j];
        float  aj = sar[w][j];
        if (v0 && j < lane) {
            float ih = fmaxf(fminf(B0.z, bj.z) - fmaxf(B0.x, bj.x), 0.f);
            float iw = fmaxf(fminf(B0.w, bj.w) - fmaxf(B0.y, bj.y), 0.f);
            float inter = ih * iw;
            if (inter > NMS_TH * fmaxf(a0 + aj - inter, 1e-8f)) m0 |= 1ull << j;
        }
        if (v1 && j < lane + 32) {
            float ih = fmaxf(fminf(B1.z, bj.z) - fmaxf(B1.x, bj.x), 0.f);
            float iw = fmaxf(fminf(B1.w, bj.w) - fmaxf(B1.y, bj.y), 0.f);
            float inter = ih * iw;
            if (inter > NMS_TH * fmaxf(a1 + aj - inter, 1e-8f)) m1 |= 1ull << j;
        }
    }
    smsk[w][lane]      = m0;
    smsk[w][lane + 32] = m1;
    __syncwarp();

    ull kept = 0;
    if (lane == 0) {
        for (int i = 0; i < cnt; i++)
            if ((smsk[w][i] & kept) == 0) kept |= 1ull << i;
    }
    kept = __shfl_sync(FULL, kept, 0);

    if (v0) g_keep[gb + i0] = (unsigned char)((kept >> lane) & 1ull);
    if (v1) g_keep[gb + i1] = (unsigned char)((kept >> (lane + 32)) & 1ull);
    if (lane == 0) g_cnt[gw] = 0;   // restore invariant for next graph replay
}

// ---------------------------------------------------------------------------
// K3: one block per batch. Histogram radix-select top-100 kept scores
// (float bits, scores in (0.7,1)), sort the <=256 survivors, emit rows.
// ---------------------------------------------------------------------------
__global__ void __launch_bounds__(1024, 1) k_select(float* __restrict__ out) {
    __shared__ float         ssc[NPAD];
    __shared__ unsigned char skp[NPAD];
    __shared__ int           hist[2048];
    __shared__ ull           cand[256];
    __shared__ int           wtot[32];
    __shared__ int           wexc[32];
    __shared__ int           s_ncand;
    __shared__ int           s_bstar;

    int b    = blockIdx.x;
    int t    = threadIdx.x;
    int w    = t >> 5;
    int lane = t & 31;
    int gb   = b * NPAD;

    float* ob = out + b * (MAXI * 6);

    for (int i = t; i < NPAD; i += 1024) {
        ssc[i]  = (i < NN) ? g_sc[gb + i]   : -1.0f;
        skp[i]  = (i < NN) ? g_keep[gb + i] : (unsigned char)0;
        hist[i] = 0;
    }
    if (t == 0) { s_ncand = 0; s_bstar = 0; }
    for (int i = t; i < MAXI * 6; i += 1024) ob[i] = 0.0f;
    __syncthreads();

    // histogram of kept scores on float bits (kept => score in (0.7,1))
    for (int i = t; i < NN; i += 1024) {
        if (skp[i]) {
            unsigned bits = __float_as_uint(ssc[i]);
            int bk = (int)((bits - 0x3F000000u) >> 12);
            bk = min(2047, max(0, bk));
            atomicAdd(&hist[bk], 1);
        }
    }
    __syncthreads();

    // suffix sums; find b* = max bucket with S[b*] >= 100
    {
        int h0 = hist[w * 64 + lane];
        int h1 = hist[w * 64 + 32 + lane];
        int s1 = h1;
        for (int d = 1; d < 32; d <<= 1) {
            int v = __shfl_down_sync(FULL, s1, d);
            if (lane + d < 32) s1 += v;
        }
        int s0 = h0;
        for (int d = 1; d < 32; d <<= 1) {
            int v = __shfl_down_sync(FULL, s0, d);
            if (lane + d < 32) s0 += v;
        }
        s0 += __shfl_sync(FULL, s1, 0);
        if (lane == 0) wtot[w] = s0;
        __syncthreads();
        if (w == 0) {
            int v = wtot[lane];
            int si = v;
            for (int d = 1; d < 32; d <<= 1) {
                int x = __shfl_down_sync(FULL, si, d);
                if (lane + d < 32) si += x;
            }
            wexc[lane] = si - v;
        }
        __syncthreads();
        int base = wexc[w];
        int S0 = s0 + base;
        int S1 = s1 + base;
        if (S0 >= MAXI && S0 - h0 < MAXI) s_bstar = w * 64 + lane;
        if (S1 >= MAXI && S1 - h1 < MAXI) s_bstar = w * 64 + 32 + lane;
    }
    __syncthreads();

    unsigned tbits = 0x3F000000u + ((unsigned)s_bstar << 12);
    for (int i = t; i < NN; i += 1024) {
        if (skp[i] && __float_as_uint(ssc[i]) >= tbits) {
            int p = atomicAdd(&s_ncand, 1);
            if (p < 256)
                cand[p] = ((ull)__float_as_uint(ssc[i]) << 32) | (ull)(0xFFFFFFFFu - (unsigned)i);
        }
    }
    __syncthreads();
    int m = min(s_ncand, 256);
    for (int i = t; i < 256; i += 1024)
        if (i >= m) cand[i] = 0;
    __syncthreads();

    for (int k = 2; k <= 256; k <<= 1) {
        for (int j = k >> 1; j > 0; j >>= 1) {
            if (t < 128) {
                int  i  = ((t & ~(j - 1)) << 1) | (t & (j - 1));
                int  p  = i | j;
                bool de = ((i & k) == 0);
                ull a = cand[i], c2 = cand[p];
                bool swp = de ? (a < c2) : (a > c2);
                if (swp) { cand[i] = c2; cand[p] = a; }
            }
            __syncthreads();
        }
    }

    int R = min(MAXI, m);
    if (t < R) {
        ull key = cand[t];
        int idx = (int)(0xFFFFFFFFu - (unsigned)key);
        float sc = __uint_as_float((unsigned)(key >> 32));
        float4 bx = g_bx[gb + idx];
        float* row = ob + t * 6;
        row[0] = bx.x; row[1] = bx.y; row[2] = bx.z; row[3] = bx.w;
        row[4] = (float)g_cl[gb + idx]; row[5] = sc;
    }
}

// ---------------------------------------------------------------------------
extern "C" void kernel_launch(void* const* d_in, const int* in_sizes, int n_in,
                              void* d_out, int out_size) {
    const float* rois   = nullptr;
    const float* probs  = nullptr;
    const float* deltas = nullptr;
    for (int i = 0; i < n_in; i++) {
        if      (in_sizes[i] == BB * NN * 4)      rois   = (const float*)d_in[i];
        else if (in_sizes[i] == BB * NN * CC)     probs  = (const float*)d_in[i];
        else if (in_sizes[i] == BB * NN * CC * 4) deltas = (const float*)d_in[i];
    }
    float* out = (float*)d_out;

    k_classify<<<(BB * NN + 7) / 8, 256>>>(rois, probs, deltas);
    k_nms     <<<(BB * 80 + 7) / 8, 256>>>();
    k_select  <<<BB, 1024>>>(out);
}